// round 7
// baseline (speedup 1.0000x reference)
#include <cuda_runtime.h>
#include <cuda_fp16.h>
#include <math.h>
#include <stdint.h>

#define EMB   1024
#define DK    64
#define BATCH 4
#define SEQ   4096
#define MROWS (BATCH * SEQ)   // 16384
#define NSPLIT 2
#define KEYS_PER_SPLIT (SEQ / NSPLIT)   // 2048

// ---------------- scratch (allocation-free) ----------------
__device__ __align__(128) __half g_q[MROWS * DK];   // [row][d], pre-scaled by 1/8
__device__ __align__(128) __half g_k[MROWS * DK];   // [row][d]
__device__ __align__(128) __half g_vt[DK * MROWS];  // [d][row]  (transposed V)
__device__ __align__(128) float  g_po[NSPLIT * MROWS * DK]; // unnormalized partial O
__device__ float g_pm[NSPLIT * MROWS];              // partial running max
__device__ float g_pl[NSPLIT * MROWS];              // partial running sum

// ---------------- helpers ----------------
__device__ __forceinline__ uint32_t packh2(float x, float y) {
    uint32_t r;
    asm("cvt.rn.f16x2.f32 %0, %1, %2;" : "=r"(r) : "f"(y), "f"(x));
    return r;
}
// fp16: D(16x8) += A(16x16) * B(16x8), fp32 accum
__device__ __forceinline__ void mma16(float* c, const uint32_t* a,
                                      uint32_t b0, uint32_t b1) {
    asm volatile(
        "mma.sync.aligned.m16n8k16.row.col.f32.f16.f16.f32 "
        "{%0,%1,%2,%3}, {%4,%5,%6,%7}, {%8,%9}, {%0,%1,%2,%3};"
        : "+f"(c[0]), "+f"(c[1]), "+f"(c[2]), "+f"(c[3])
        : "r"(a[0]), "r"(a[1]), "r"(a[2]), "r"(a[3]), "r"(b0), "r"(b1));
}

// ============================================================
// Projection GEMM (fp16 mma): C[16384,64] = X @ W + b
// BM=128, BN=64, BK=64, 8 warps, 16 outer iterations.
// ============================================================
#define XP 72   // pitch in halfs (144 B): frag LDS conflict-free

__global__ __launch_bounds__(256) void proj_fp16(
    const float* __restrict__ in1, const float* __restrict__ in2,
    const float* __restrict__ Wq, const float* __restrict__ bq,
    const float* __restrict__ Wk, const float* __restrict__ bk,
    const float* __restrict__ Wv, const float* __restrict__ bv)
{
    __shared__ __align__(16) __half Xs[128 * XP];
    __shared__ __align__(16) __half Ws[64 * XP];   // W^T tile: [n][k]

    const int which = blockIdx.z;
    const float* X    = (which == 0) ? in2 : in1;
    const float* W    = (which == 0) ? Wq : (which == 1 ? Wk : Wv);
    const float* bias = (which == 0) ? bq : (which == 1 ? bk : bv);

    const int m0   = blockIdx.x * 128;
    const int tid  = threadIdx.x;
    const int warp = tid >> 5;
    const int lane = tid & 31;
    const int g    = lane >> 2;
    const int t4   = lane & 3;
    const int wm   = warp * 16;

    float acc[8][4];
    #pragma unroll
    for (int nt = 0; nt < 8; nt++)
        #pragma unroll
        for (int j = 0; j < 4; j++) acc[nt][j] = 0.f;

    for (int kt = 0; kt < EMB; kt += 64) {
        // ---- X tile 128x64 -> fp16 smem ----
        #pragma unroll
        for (int it = 0; it < 8; it++) {
            int idx = tid + it * 256;            // 2048 float4
            int r = idx >> 4, c4 = (idx & 15) * 4;
            float4 v = *(const float4*)(X + (size_t)(m0 + r) * EMB + kt + c4);
            uint2 p = {packh2(v.x, v.y), packh2(v.z, v.w)};
            *(uint2*)&Xs[r * XP + c4] = p;
        }
        // ---- W^T tile 64(n) x 64(k) -> fp16 smem ----
        #pragma unroll
        for (int it = 0; it < 4; it++) {
            int idx = tid + it * 256;            // 1024 float4
            int k = idx >> 4, n4 = (idx & 15) * 4;
            float4 v = *(const float4*)(W + (size_t)(kt + k) * DK + n4);
            Ws[(n4 + 0) * XP + k] = __float2half_rn(v.x);
            Ws[(n4 + 1) * XP + k] = __float2half_rn(v.y);
            Ws[(n4 + 2) * XP + k] = __float2half_rn(v.z);
            Ws[(n4 + 3) * XP + k] = __float2half_rn(v.w);
        }
        __syncthreads();

        #pragma unroll
        for (int ks = 0; ks < 4; ks++) {
            uint32_t a[4];
            a[0] = *(const uint32_t*)&Xs[(wm + g    ) * XP + ks * 16 + 2 * t4    ];
            a[1] = *(const uint32_t*)&Xs[(wm + g + 8) * XP + ks * 16 + 2 * t4    ];
            a[2] = *(const uint32_t*)&Xs[(wm + g    ) * XP + ks * 16 + 2 * t4 + 8];
            a[3] = *(const uint32_t*)&Xs[(wm + g + 8) * XP + ks * 16 + 2 * t4 + 8];
            #pragma unroll
            for (int nt = 0; nt < 8; nt++) {
                uint32_t b0 = *(const uint32_t*)&Ws[(nt * 8 + g) * XP + ks * 16 + 2 * t4    ];
                uint32_t b1 = *(const uint32_t*)&Ws[(nt * 8 + g) * XP + ks * 16 + 2 * t4 + 8];
                mma16(acc[nt], a, b0, b1);
            }
        }
        __syncthreads();
    }

    // epilogue -> fp16 (Q pre-scaled; V transposed)
    #pragma unroll
    for (int nt = 0; nt < 8; nt++) {
        const int col = nt * 8 + 2 * t4;
        const float b0 = bias[col], b1 = bias[col + 1];
        const int rowA = m0 + wm + g, rowB = rowA + 8;
        float a0 = acc[nt][0] + b0, a1 = acc[nt][1] + b1;
        float a2 = acc[nt][2] + b0, a3 = acc[nt][3] + b1;
        if (which == 0) {
            *(uint32_t*)(g_q + (size_t)rowA * DK + col) = packh2(a0 * 0.125f, a1 * 0.125f);
            *(uint32_t*)(g_q + (size_t)rowB * DK + col) = packh2(a2 * 0.125f, a3 * 0.125f);
        } else if (which == 1) {
            *(uint32_t*)(g_k + (size_t)rowA * DK + col) = packh2(a0, a1);
            *(uint32_t*)(g_k + (size_t)rowB * DK + col) = packh2(a2, a3);
        } else {
            g_vt[(size_t)(col    ) * MROWS + rowA] = __float2half_rn(a0);
            g_vt[(size_t)(col + 1) * MROWS + rowA] = __float2half_rn(a1);
            g_vt[(size_t)(col    ) * MROWS + rowB] = __float2half_rn(a2);
            g_vt[(size_t)(col + 1) * MROWS + rowB] = __float2half_rn(a3);
        }
    }
}

// ============================================================
// Flash attention, fp16 m16n8k16, split-KV x2.
// CTA: 128 thr (4 warps x 16 q-rows = 64 q), 2048 keys per CTA.
// ============================================================
#define FP 88            // smem pitch in halfs (176 B)
#define FPB 176

__global__ __launch_bounds__(128) void flash_fp16()
{
    __shared__ __align__(16) __half Ks[64 * FP];   // [key][d]
    __shared__ __align__(16) __half Vs[64 * FP];   // [d][key]

    const int tid  = threadIdx.x;
    const int warp = tid >> 5;
    const int lane = tid & 31;
    const int g    = lane >> 2;
    const int t4   = lane & 3;
    const int b    = blockIdx.y;
    const int sp   = blockIdx.z;
    const int q0   = blockIdx.x * 64 + warp * 16;
    const int kt0  = sp * KEYS_PER_SPLIT;

    // ---- Q fragments (already scaled by 1/8) ----
    uint32_t q[16];
    {
        const __half* Qg = g_q + (size_t)(b * SEQ + q0) * DK;
        #pragma unroll
        for (int ks = 0; ks < 4; ks++) {
            q[ks * 4 + 0] = *(const uint32_t*)(Qg + (size_t)(g    ) * DK + ks * 16 + 2 * t4    );
            q[ks * 4 + 1] = *(const uint32_t*)(Qg + (size_t)(g + 8) * DK + ks * 16 + 2 * t4    );
            q[ks * 4 + 2] = *(const uint32_t*)(Qg + (size_t)(g    ) * DK + ks * 16 + 2 * t4 + 8);
            q[ks * 4 + 3] = *(const uint32_t*)(Qg + (size_t)(g + 8) * DK + ks * 16 + 2 * t4 + 8);
        }
    }

    float o[8][4];
    #pragma unroll
    for (int nt = 0; nt < 8; nt++)
        #pragma unroll
        for (int j = 0; j < 4; j++) o[nt][j] = 0.f;
    float mA = -INFINITY, mB = -INFINITY, lA = 0.f, lB = 0.f;

    const __half* Kg0 = g_k + (size_t)(b * SEQ) * DK;

    for (int kt = kt0; kt < kt0 + KEYS_PER_SPLIT; kt += 64) {
        __syncthreads();

        // ---- load K[64 keys][64 d] and Vt[64 d][64 keys] ----
        {
            const char* Kg = (const char*)(Kg0 + (size_t)kt * DK);
            const __half* Vg = g_vt + (size_t)(b * SEQ + kt);
            #pragma unroll
            for (int it = 0; it < 4; it++) {
                int i = tid + it * 128;        // 512 uint4
                int r = i >> 3, c = i & 7;
                *(uint4*)((char*)Ks + r * FPB + c * 16) =
                    *(const uint4*)(Kg + r * 128 + c * 16);
                *(uint4*)((char*)Vs + r * FPB + c * 16) =
                    *(const uint4*)((const char*)(Vg + (size_t)r * MROWS) + c * 16);
            }
        }
        __syncthreads();

        // ---- S = Q @ K^T ----
        float s[8][4];
        #pragma unroll
        for (int nt = 0; nt < 8; nt++)
            #pragma unroll
            for (int j = 0; j < 4; j++) s[nt][j] = 0.f;

        #pragma unroll
        for (int ks = 0; ks < 4; ks++) {
            #pragma unroll
            for (int nt = 0; nt < 8; nt++) {
                const char* kb = (const char*)Ks + (nt * 8 + g) * FPB + ks * 32 + t4 * 4;
                uint32_t b0 = *(const uint32_t*)kb;
                uint32_t b1 = *(const uint32_t*)(kb + 16);
                mma16(s[nt], &q[ks * 4], b0, b1);
            }
        }

        // ---- online softmax ----
        float mxA = -INFINITY, mxB = -INFINITY;
        #pragma unroll
        for (int nt = 0; nt < 8; nt++) {
            mxA = fmaxf(mxA, fmaxf(s[nt][0], s[nt][1]));
            mxB = fmaxf(mxB, fmaxf(s[nt][2], s[nt][3]));
        }
        mxA = fmaxf(mxA, __shfl_xor_sync(0xffffffffu, mxA, 1));
        mxA = fmaxf(mxA, __shfl_xor_sync(0xffffffffu, mxA, 2));
        mxB = fmaxf(mxB, __shfl_xor_sync(0xffffffffu, mxB, 1));
        mxB = fmaxf(mxB, __shfl_xor_sync(0xffffffffu, mxB, 2));

        const float mnA = fmaxf(mA, mxA), mnB = fmaxf(mB, mxB);
        const float cA = __expf(mA - mnA), cB = __expf(mB - mnB);

        float sumA = 0.f, sumB = 0.f;
        #pragma unroll
        for (int nt = 0; nt < 8; nt++) {
            s[nt][0] = __expf(s[nt][0] - mnA);
            s[nt][1] = __expf(s[nt][1] - mnA);
            s[nt][2] = __expf(s[nt][2] - mnB);
            s[nt][3] = __expf(s[nt][3] - mnB);
            sumA += s[nt][0] + s[nt][1];
            sumB += s[nt][2] + s[nt][3];
        }
        sumA += __shfl_xor_sync(0xffffffffu, sumA, 1);
        sumA += __shfl_xor_sync(0xffffffffu, sumA, 2);
        sumB += __shfl_xor_sync(0xffffffffu, sumB, 1);
        sumB += __shfl_xor_sync(0xffffffffu, sumB, 2);
        lA = lA * cA + sumA;  mA = mnA;
        lB = lB * cB + sumB;  mB = mnB;

        #pragma unroll
        for (int nt = 0; nt < 8; nt++) {
            o[nt][0] *= cA; o[nt][1] *= cA;
            o[nt][2] *= cB; o[nt][3] *= cB;
        }

        // ---- O += P @ V : S frags reused as A frags ----
        #pragma unroll
        for (int ks = 0; ks < 4; ks++) {
            uint32_t a[4];
            a[0] = packh2(s[2 * ks    ][0], s[2 * ks    ][1]);
            a[1] = packh2(s[2 * ks    ][2], s[2 * ks    ][3]);
            a[2] = packh2(s[2 * ks + 1][0], s[2 * ks + 1][1]);
            a[3] = packh2(s[2 * ks + 1][2], s[2 * ks + 1][3]);
            #pragma unroll
            for (int nt = 0; nt < 8; nt++) {
                const char* vb = (const char*)Vs + (nt * 8 + g) * FPB + ks * 32 + t4 * 4;
                uint32_t b0 = *(const uint32_t*)vb;
                uint32_t b1 = *(const uint32_t*)(vb + 16);
                mma16(o[nt], a, b0, b1);
            }
        }
    }

    // ---- epilogue: unnormalized partials to scratch ----
    const int rowA = b * SEQ + q0 + g;
    const int rowB = rowA + 8;
    float* poA = g_po + ((size_t)sp * MROWS + rowA) * DK;
    float* poB = g_po + ((size_t)sp * MROWS + rowB) * DK;
    #pragma unroll
    for (int nt = 0; nt < 8; nt++) {
        const int col = nt * 8 + 2 * t4;
        float2 oa = {o[nt][0], o[nt][1]};
        float2 ob = {o[nt][2], o[nt][3]};
        *(float2*)(poA + col) = oa;
        *(float2*)(poB + col) = ob;
    }
    if (t4 == 0) {
        g_pm[sp * MROWS + rowA] = mA;  g_pl[sp * MROWS + rowA] = lA;
        g_pm[sp * MROWS + rowB] = mB;  g_pl[sp * MROWS + rowB] = lB;
    }
}

// ============================================================
// Merge the NSPLIT partials -> final normalized output
// ============================================================
__global__ __launch_bounds__(256) void merge_splits(float* __restrict__ out)
{
    const int i = blockIdx.x * 256 + threadIdx.x;     // over MROWS*16 float4
    const int row = i >> 4, c4 = (i & 15) * 4;

    const float m1 = g_pm[row],        l1 = g_pl[row];
    const float m2 = g_pm[MROWS + row], l2 = g_pl[MROWS + row];
    const float m  = fmaxf(m1, m2);
    const float w1 = __expf(m1 - m), w2 = __expf(m2 - m);
    const float inv = 1.f / (w1 * l1 + w2 * l2);

    const float4 o1 = *(const float4*)(g_po + (size_t)row * DK + c4);
    const float4 o2 = *(const float4*)(g_po + ((size_t)MROWS + row) * DK + c4);
    float4 r;
    r.x = (w1 * o1.x + w2 * o2.x) * inv;
    r.y = (w1 * o1.y + w2 * o2.y) * inv;
    r.z = (w1 * o1.z + w2 * o2.z) * inv;
    r.w = (w1 * o1.w + w2 * o2.w) * inv;
    *(float4*)(out + (size_t)row * DK + c4) = r;
}

// ---------------- launch ----------------
extern "C" void kernel_launch(void* const* d_in, const int* in_sizes, int n_in,
                              void* d_out, int out_size)
{
    const float* input1 = (const float*)d_in[0];
    const float* input2 = (const float*)d_in[1];
    const float* Wq = (const float*)d_in[2];
    const float* bq = (const float*)d_in[3];
    const float* Wk = (const float*)d_in[4];
    const float* bk = (const float*)d_in[5];
    const float* Wv = (const float*)d_in[6];
    const float* bv = (const float*)d_in[7];
    float* out = (float*)d_out;

    (void)in_sizes; (void)n_in; (void)out_size;

    dim3 pgrid(MROWS / 128, 1, 3);
    proj_fp16<<<pgrid, 256>>>(input1, input2, Wq, bq, Wk, bk, Wv, bv);

    dim3 fgrid(SEQ / 64, BATCH, NSPLIT);
    flash_fp16<<<fgrid, 128>>>();

    merge_splits<<<(MROWS * 16) / 256, 256>>>(out);
}

// round 8
// speedup vs baseline: 1.1300x; 1.1300x over previous
#include <cuda_runtime.h>
#include <cuda_fp16.h>
#include <math.h>
#include <stdint.h>

#define EMB   1024
#define DK    64
#define BATCH 4
#define SEQ   4096
#define MROWS (BATCH * SEQ)   // 16384
#define NSPLIT 4
#define KEYS_PER_SPLIT (SEQ / NSPLIT)   // 1024

// ---------------- scratch (allocation-free) ----------------
__device__ __align__(128) __half g_q[MROWS * DK];    // [row][d], pre-scaled 1/8
__device__ __align__(128) __half g_k[MROWS * DK];    // [row][d]
__device__ __align__(128) __half g_vt[DK * MROWS];   // [d][row]
__device__ __align__(128) __half g_wt[3 * DK * EMB]; // W^T fp16: [which][n][k]
__device__ __align__(128) float  g_po[NSPLIT * MROWS * DK];
__device__ float g_pm[NSPLIT * MROWS];
__device__ float g_pl[NSPLIT * MROWS];

// ---------------- helpers ----------------
__device__ __forceinline__ uint32_t packh2(float x, float y) {
    uint32_t r;
    asm("cvt.rn.f16x2.f32 %0, %1, %2;" : "=r"(r) : "f"(y), "f"(x));
    return r;
}
// fp16: D(16x8) += A(16x16) * B(16x8), fp32 accum
__device__ __forceinline__ void mma16(float* c, const uint32_t* a,
                                      uint32_t b0, uint32_t b1) {
    asm volatile(
        "mma.sync.aligned.m16n8k16.row.col.f32.f16.f16.f32 "
        "{%0,%1,%2,%3}, {%4,%5,%6,%7}, {%8,%9}, {%0,%1,%2,%3};"
        : "+f"(c[0]), "+f"(c[1]), "+f"(c[2]), "+f"(c[3])
        : "r"(a[0]), "r"(a[1]), "r"(a[2]), "r"(a[3]), "r"(b0), "r"(b1));
}

// ============================================================
// prep_w: W[1024,64] fp32 -> g_wt[which][n][k] fp16 (once)
// ============================================================
__global__ __launch_bounds__(256) void prep_w(
    const float* __restrict__ Wq, const float* __restrict__ Wk,
    const float* __restrict__ Wv)
{
    const int idx = blockIdx.x * 256 + threadIdx.x;  // 3*64*256 = 49152
    const int which = idx >> 14;
    const int n  = (idx >> 8) & 63;
    const int k4 = (idx & 255) * 4;
    const float* W = (which == 0) ? Wq : (which == 1 ? Wk : Wv);
    uint2 p;
    p.x = packh2(W[(size_t)(k4 + 0) * DK + n], W[(size_t)(k4 + 1) * DK + n]);
    p.y = packh2(W[(size_t)(k4 + 2) * DK + n], W[(size_t)(k4 + 3) * DK + n]);
    *(uint2*)(g_wt + ((size_t)which * DK + n) * EMB + k4) = p;
}

// ============================================================
// Fused projection: z=0 -> Q (N=64, X=input2); z=1 -> K|V (N=128, X=input1)
// BM=128, BK=64, 8 warps.
// ============================================================
#define XP  72      // pitch in halfs (144 B)
#define XPB 144

template<int NT>
__device__ __forceinline__ void proj_body(
    const float* __restrict__ X, const __half* Xs, __half* Ws,
    int which, int m0, int tid, int warp, int lane,
    const float* __restrict__ bq, const float* __restrict__ bk,
    const float* __restrict__ bv)
{
    const int g  = lane >> 2;
    const int t4 = lane & 3;
    const int wm = warp * 16;

    float acc[NT][4];
    #pragma unroll
    for (int nt = 0; nt < NT; nt++)
        #pragma unroll
        for (int j = 0; j < 4; j++) acc[nt][j] = 0.f;

    __half* XsW = (__half*)Xs;   // non-const for stores

    for (int kt = 0; kt < EMB; kt += 64) {
        // ---- X tile 128x64 -> fp16 smem ----
        #pragma unroll
        for (int it = 0; it < 8; it++) {
            int idx = tid + it * 256;
            int r = idx >> 4, c4 = (idx & 15) * 4;
            float4 v = *(const float4*)(X + (size_t)(m0 + r) * EMB + kt + c4);
            uint2 p = {packh2(v.x, v.y), packh2(v.z, v.w)};
            *(uint2*)&XsW[r * XP + c4] = p;
        }
        // ---- W^T tile: straight uint4 copy from g_wt ----
        #pragma unroll
        for (int it = 0; it < NT; it++) {        // NT*8 uint4s per 256 thr... loop count = NT*8*? 
            int i = tid + it * 256;
            if (i < NT * 8 * 8) {
                int r = i >> 3, c = i & 7;       // r: 0..NT*8-1 rows, c: 8 uint4/row
                int wsel = (which == 0) ? 0 : (r < 64 ? 1 : 2);
                const __half* src = g_wt + ((size_t)wsel * DK + (r & 63)) * EMB + kt + c * 8;
                *(uint4*)((char*)Ws + r * XPB + c * 16) = *(const uint4*)src;
            }
        }
        __syncthreads();

        #pragma unroll
        for (int ks = 0; ks < 4; ks++) {
            uint32_t a[4];
            a[0] = *(const uint32_t*)&Xs[(wm + g    ) * XP + ks * 16 + 2 * t4    ];
            a[1] = *(const uint32_t*)&Xs[(wm + g + 8) * XP + ks * 16 + 2 * t4    ];
            a[2] = *(const uint32_t*)&Xs[(wm + g    ) * XP + ks * 16 + 2 * t4 + 8];
            a[3] = *(const uint32_t*)&Xs[(wm + g + 8) * XP + ks * 16 + 2 * t4 + 8];
            #pragma unroll
            for (int nt = 0; nt < NT; nt++) {
                uint32_t b0 = *(const uint32_t*)&Ws[(nt * 8 + g) * XP + ks * 16 + 2 * t4    ];
                uint32_t b1 = *(const uint32_t*)&Ws[(nt * 8 + g) * XP + ks * 16 + 2 * t4 + 8];
                mma16(acc[nt], a, b0, b1);
            }
        }
        __syncthreads();
    }

    // ---- epilogue ----
    #pragma unroll
    for (int nt = 0; nt < NT; nt++) {
        const int col = (nt & 7) * 8 + 2 * t4;
        const int rowA = m0 + wm + g, rowB = rowA + 8;
        if (which == 0) {
            const float b0 = bq[col], b1 = bq[col + 1];
            float a0 = (acc[nt][0] + b0) * 0.125f, a1 = (acc[nt][1] + b1) * 0.125f;
            float a2 = (acc[nt][2] + b0) * 0.125f, a3 = (acc[nt][3] + b1) * 0.125f;
            *(uint32_t*)(g_q + (size_t)rowA * DK + col) = packh2(a0, a1);
            *(uint32_t*)(g_q + (size_t)rowB * DK + col) = packh2(a2, a3);
        } else if (nt < 8) {
            const float b0 = bk[col], b1 = bk[col + 1];
            *(uint32_t*)(g_k + (size_t)rowA * DK + col) = packh2(acc[nt][0] + b0, acc[nt][1] + b1);
            *(uint32_t*)(g_k + (size_t)rowB * DK + col) = packh2(acc[nt][2] + b0, acc[nt][3] + b1);
        } else {
            const float b0 = bv[col], b1 = bv[col + 1];
            g_vt[(size_t)(col    ) * MROWS + rowA] = __float2half_rn(acc[nt][0] + b0);
            g_vt[(size_t)(col + 1) * MROWS + rowA] = __float2half_rn(acc[nt][1] + b1);
            g_vt[(size_t)(col    ) * MROWS + rowB] = __float2half_rn(acc[nt][2] + b0);
            g_vt[(size_t)(col + 1) * MROWS + rowB] = __float2half_rn(acc[nt][3] + b1);
        }
    }
}

__global__ __launch_bounds__(256) void proj_fused(
    const float* __restrict__ in1, const float* __restrict__ in2,
    const float* __restrict__ bq, const float* __restrict__ bk,
    const float* __restrict__ bv)
{
    __shared__ __align__(16) __half Xs[128 * XP];
    __shared__ __align__(16) __half Ws[128 * XP];

    const int which = blockIdx.z;
    const float* X = (which == 0) ? in2 : in1;
    const int m0   = blockIdx.x * 128;
    const int tid  = threadIdx.x;
    const int warp = tid >> 5;
    const int lane = tid & 31;

    if (which == 0)
        proj_body<8>(X, Xs, Ws, 0, m0, tid, warp, lane, bq, bk, bv);
    else
        proj_body<16>(X, Xs, Ws, 1, m0, tid, warp, lane, bq, bk, bv);
}

// ============================================================
// Flash attention, fp16 m16n8k16, split-KV x4.
// CTA: 128 thr (4 warps x 16 q-rows = 64 q), 1024 keys per CTA.
// ============================================================
#define FP 88
#define FPB 176

__global__ __launch_bounds__(128) void flash_fp16()
{
    __shared__ __align__(16) __half Ks[64 * FP];   // [key][d]
    __shared__ __align__(16) __half Vs[64 * FP];   // [d][key]

    const int tid  = threadIdx.x;
    const int warp = tid >> 5;
    const int lane = tid & 31;
    const int g    = lane >> 2;
    const int t4   = lane & 3;
    const int b    = blockIdx.y;
    const int sp   = blockIdx.z;
    const int q0   = blockIdx.x * 64 + warp * 16;
    const int kt0  = sp * KEYS_PER_SPLIT;

    // ---- Q fragments (scaled by 1/8 already) ----
    uint32_t q[16];
    {
        const __half* Qg = g_q + (size_t)(b * SEQ + q0) * DK;
        #pragma unroll
        for (int ks = 0; ks < 4; ks++) {
            q[ks * 4 + 0] = *(const uint32_t*)(Qg + (size_t)(g    ) * DK + ks * 16 + 2 * t4    );
            q[ks * 4 + 1] = *(const uint32_t*)(Qg + (size_t)(g + 8) * DK + ks * 16 + 2 * t4    );
            q[ks * 4 + 2] = *(const uint32_t*)(Qg + (size_t)(g    ) * DK + ks * 16 + 2 * t4 + 8);
            q[ks * 4 + 3] = *(const uint32_t*)(Qg + (size_t)(g + 8) * DK + ks * 16 + 2 * t4 + 8);
        }
    }

    float o[8][4];
    #pragma unroll
    for (int nt = 0; nt < 8; nt++)
        #pragma unroll
        for (int j = 0; j < 4; j++) o[nt][j] = 0.f;
    float mA = -INFINITY, mB = -INFINITY, lA = 0.f, lB = 0.f;

    const __half* Kg0 = g_k + (size_t)(b * SEQ) * DK;

    for (int kt = kt0; kt < kt0 + KEYS_PER_SPLIT; kt += 64) {
        __syncthreads();
        {
            const char* Kg = (const char*)(Kg0 + (size_t)kt * DK);
            const __half* Vg = g_vt + (size_t)(b * SEQ + kt);
            #pragma unroll
            for (int it = 0; it < 4; it++) {
                int i = tid + it * 128;
                int r = i >> 3, c = i & 7;
                *(uint4*)((char*)Ks + r * FPB + c * 16) =
                    *(const uint4*)(Kg + r * 128 + c * 16);
                *(uint4*)((char*)Vs + r * FPB + c * 16) =
                    *(const uint4*)((const char*)(Vg + (size_t)r * MROWS) + c * 16);
            }
        }
        __syncthreads();

        // ---- S = Q @ K^T ----
        float s[8][4];
        #pragma unroll
        for (int nt = 0; nt < 8; nt++)
            #pragma unroll
            for (int j = 0; j < 4; j++) s[nt][j] = 0.f;

        #pragma unroll
        for (int ks = 0; ks < 4; ks++) {
            #pragma unroll
            for (int nt = 0; nt < 8; nt++) {
                const char* kb = (const char*)Ks + (nt * 8 + g) * FPB + ks * 32 + t4 * 4;
                uint32_t b0 = *(const uint32_t*)kb;
                uint32_t b1 = *(const uint32_t*)(kb + 16);
                mma16(s[nt], &q[ks * 4], b0, b1);
            }
        }

        // ---- online softmax ----
        float mxA = -INFINITY, mxB = -INFINITY;
        #pragma unroll
        for (int nt = 0; nt < 8; nt++) {
            mxA = fmaxf(mxA, fmaxf(s[nt][0], s[nt][1]));
            mxB = fmaxf(mxB, fmaxf(s[nt][2], s[nt][3]));
        }
        mxA = fmaxf(mxA, __shfl_xor_sync(0xffffffffu, mxA, 1));
        mxA = fmaxf(mxA, __shfl_xor_sync(0xffffffffu, mxA, 2));
        mxB = fmaxf(mxB, __shfl_xor_sync(0xffffffffu, mxB, 1));
        mxB = fmaxf(mxB, __shfl_xor_sync(0xffffffffu, mxB, 2));

        const float mnA = fmaxf(mA, mxA), mnB = fmaxf(mB, mxB);
        const float cA = __expf(mA - mnA), cB = __expf(mB - mnB);

        float sumA = 0.f, sumB = 0.f;
        #pragma unroll
        for (int nt = 0; nt < 8; nt++) {
            s[nt][0] = __expf(s[nt][0] - mnA);
            s[nt][1] = __expf(s[nt][1] - mnA);
            s[nt][2] = __expf(s[nt][2] - mnB);
            s[nt][3] = __expf(s[nt][3] - mnB);
            sumA += s[nt][0] + s[nt][1];
            sumB += s[nt][2] + s[nt][3];
        }
        sumA += __shfl_xor_sync(0xffffffffu, sumA, 1);
        sumA += __shfl_xor_sync(0xffffffffu, sumA, 2);
        sumB += __shfl_xor_sync(0xffffffffu, sumB, 1);
        sumB += __shfl_xor_sync(0xffffffffu, sumB, 2);
        lA = lA * cA + sumA;  mA = mnA;
        lB = lB * cB + sumB;  mB = mnB;

        #pragma unroll
        for (int nt = 0; nt < 8; nt++) {
            o[nt][0] *= cA; o[nt][1] *= cA;
            o[nt][2] *= cB; o[nt][3] *= cB;
        }

        // ---- O += P @ V ----
        #pragma unroll
        for (int ks = 0; ks < 4; ks++) {
            uint32_t a[4];
            a[0] = packh2(s[2 * ks    ][0], s[2 * ks    ][1]);
            a[1] = packh2(s[2 * ks    ][2], s[2 * ks    ][3]);
            a[2] = packh2(s[2 * ks + 1][0], s[2 * ks + 1][1]);
            a[3] = packh2(s[2 * ks + 1][2], s[2 * ks + 1][3]);
            #pragma unroll
            for (int nt = 0; nt < 8; nt++) {
                const char* vb = (const char*)Vs + (nt * 8 + g) * FPB + ks * 32 + t4 * 4;
                uint32_t b0 = *(const uint32_t*)vb;
                uint32_t b1 = *(const uint32_t*)(vb + 16);
                mma16(o[nt], a, b0, b1);
            }
        }
    }

    // ---- epilogue: unnormalized partials ----
    const int rowA = b * SEQ + q0 + g;
    const int rowB = rowA + 8;
    float* poA = g_po + ((size_t)sp * MROWS + rowA) * DK;
    float* poB = g_po + ((size_t)sp * MROWS + rowB) * DK;
    #pragma unroll
    for (int nt = 0; nt < 8; nt++) {
        const int col = nt * 8 + 2 * t4;
        *(float2*)(poA + col) = make_float2(o[nt][0], o[nt][1]);
        *(float2*)(poB + col) = make_float2(o[nt][2], o[nt][3]);
    }
    if (t4 == 0) {
        g_pm[sp * MROWS + rowA] = mA;  g_pl[sp * MROWS + rowA] = lA;
        g_pm[sp * MROWS + rowB] = mB;  g_pl[sp * MROWS + rowB] = lB;
    }
}

// ============================================================
// Merge NSPLIT partials -> final normalized output
// ============================================================
__global__ __launch_bounds__(256) void merge_splits(float* __restrict__ out)
{
    const int i = blockIdx.x * 256 + threadIdx.x;
    const int row = i >> 4, c4 = (i & 15) * 4;

    float m = -INFINITY;
    #pragma unroll
    for (int s = 0; s < NSPLIT; s++)
        m = fmaxf(m, g_pm[s * MROWS + row]);

    float lsum = 0.f;
    float4 acc = {0.f, 0.f, 0.f, 0.f};
    #pragma unroll
    for (int s = 0; s < NSPLIT; s++) {
        const float w = __expf(g_pm[s * MROWS + row] - m);
        lsum += w * g_pl[s * MROWS + row];
        const float4 o = *(const float4*)(g_po + ((size_t)s * MROWS + row) * DK + c4);
        acc.x += w * o.x; acc.y += w * o.y;
        acc.z += w * o.z; acc.w += w * o.w;
    }
    const float inv = 1.f / lsum;
    float4 r = {acc.x * inv, acc.y * inv, acc.z * inv, acc.w * inv};
    *(float4*)(out + (size_t)row * DK + c4) = r;
}

// ---------------- launch ----------------
extern "C" void kernel_launch(void* const* d_in, const int* in_sizes, int n_in,
                              void* d_out, int out_size)
{
    const float* input1 = (const float*)d_in[0];
    const float* input2 = (const float*)d_in[1];
    const float* Wq = (const float*)d_in[2];
    const float* bq = (const float*)d_in[3];
    const float* Wk = (const float*)d_in[4];
    const float* bk = (const float*)d_in[5];
    const float* Wv = (const float*)d_in[6];
    const float* bv = (const float*)d_in[7];
    float* out = (float*)d_out;

    (void)in_sizes; (void)n_in; (void)out_size;

    prep_w<<<192, 256>>>(Wq, Wk, Wv);

    dim3 pgrid(MROWS / 128, 1, 2);
    proj_fused<<<pgrid, 256>>>(input1, input2, bq, bk, bv);

    dim3 fgrid(SEQ / 64, BATCH, NSPLIT);
    flash_fp16<<<fgrid, 128>>>();

    merge_splits<<<(MROWS * 16) / 256, 256>>>(out);
}

// round 9
// speedup vs baseline: 1.3091x; 1.1584x over previous
#include <cuda_runtime.h>
#include <cuda_fp16.h>
#include <math.h>
#include <stdint.h>

#define EMB   1024
#define DK    64
#define BATCH 4
#define SEQ   4096
#define MROWS (BATCH * SEQ)   // 16384
#define NSPLIT 4
#define KEYS_PER_SPLIT (SEQ / NSPLIT)   // 1024
#define NTILES (KEYS_PER_SPLIT / 64)    // 16

// ---------------- scratch (allocation-free) ----------------
__device__ __align__(128) __half g_q[MROWS * DK];    // [row][d], pre-scaled 1/8
__device__ __align__(128) __half g_k[MROWS * DK];    // [row][d]
__device__ __align__(128) __half g_vt[DK * MROWS];   // [d][row]
__device__ __align__(128) __half g_wt[3 * DK * EMB]; // W^T fp16: [which][n][k]
__device__ __align__(128) float  g_po[NSPLIT * MROWS * DK];
__device__ float g_pm[NSPLIT * MROWS];
__device__ float g_pl[NSPLIT * MROWS];

// ---------------- helpers ----------------
__device__ __forceinline__ uint32_t packh2(float x, float y) {
    uint32_t r;
    asm("cvt.rn.f16x2.f32 %0, %1, %2;" : "=r"(r) : "f"(y), "f"(x));
    return r;
}
__device__ __forceinline__ uint32_t smem_u32(const void* p) {
    uint32_t a;
    asm("{ .reg .u64 t; cvta.to.shared.u64 t, %1; cvt.u32.u64 %0, t; }" : "=r"(a) : "l"(p));
    return a;
}
__device__ __forceinline__ void cpa16(uint32_t s, const void* g) {
    asm volatile("cp.async.cg.shared.global [%0], [%1], 16;" :: "r"(s), "l"(g));
}
// fp16: D(16x8) += A(16x16) * B(16x8), fp32 accum
__device__ __forceinline__ void mma16(float* c, const uint32_t* a,
                                      uint32_t b0, uint32_t b1) {
    asm volatile(
        "mma.sync.aligned.m16n8k16.row.col.f32.f16.f16.f32 "
        "{%0,%1,%2,%3}, {%4,%5,%6,%7}, {%8,%9}, {%0,%1,%2,%3};"
        : "+f"(c[0]), "+f"(c[1]), "+f"(c[2]), "+f"(c[3])
        : "r"(a[0]), "r"(a[1]), "r"(a[2]), "r"(a[3]), "r"(b0), "r"(b1));
}

// ============================================================
// prep_w: W[1024,64] fp32 -> g_wt[which][n][k] fp16 (once)
// ============================================================
__global__ __launch_bounds__(256) void prep_w(
    const float* __restrict__ Wq, const float* __restrict__ Wk,
    const float* __restrict__ Wv)
{
    const int idx = blockIdx.x * 256 + threadIdx.x;  // 49152
    const int which = idx >> 14;
    const int n  = (idx >> 8) & 63;
    const int k4 = (idx & 255) * 4;
    const float* W = (which == 0) ? Wq : (which == 1 ? Wk : Wv);
    uint2 p;
    p.x = packh2(W[(size_t)(k4 + 0) * DK + n], W[(size_t)(k4 + 1) * DK + n]);
    p.y = packh2(W[(size_t)(k4 + 2) * DK + n], W[(size_t)(k4 + 3) * DK + n]);
    *(uint2*)(g_wt + ((size_t)which * DK + n) * EMB + k4) = p;
}

// ============================================================
// Fused projection: z=0 -> Q (N=64, X=input2); z=1 -> K|V (N=128, X=input1)
// BM=128, BK=64, 8 warps, register-prefetched X.
// ============================================================
#define XP  72
#define XPB 144

template<int NT>
__device__ __forceinline__ void proj_body(
    const float* __restrict__ X, __half* Xs, __half* Ws,
    int which, int m0, int tid, int warp, int lane,
    const float* __restrict__ bq, const float* __restrict__ bk,
    const float* __restrict__ bv)
{
    const int g  = lane >> 2;
    const int t4 = lane & 3;
    const int wm = warp * 16;

    float acc[NT][4];
    #pragma unroll
    for (int nt = 0; nt < NT; nt++)
        #pragma unroll
        for (int j = 0; j < 4; j++) acc[nt][j] = 0.f;

    // prologue: prefetch X tile 0 (packed to half2 immediately)
    uint2 xp[8];
    #pragma unroll
    for (int it = 0; it < 8; it++) {
        int idx = tid + it * 256;
        int r = idx >> 4, c4 = (idx & 15) * 4;
        float4 v = *(const float4*)(X + (size_t)(m0 + r) * EMB + c4);
        xp[it].x = packh2(v.x, v.y);
        xp[it].y = packh2(v.z, v.w);
    }

    for (int kt = 0; kt < EMB; kt += 64) {
        // ---- store prefetched X tile ----
        #pragma unroll
        for (int it = 0; it < 8; it++) {
            int idx = tid + it * 256;
            int r = idx >> 4, c4 = (idx & 15) * 4;
            *(uint2*)&Xs[r * XP + c4] = xp[it];
        }
        // ---- W^T tile: straight uint4 copy from g_wt ----
        #pragma unroll
        for (int it = 0; it < NT / 4; it++) {
            int i = tid + it * 256;
            int r = i >> 3, c = i & 7;
            int wsel = (which == 0) ? 0 : (r < 64 ? 1 : 2);
            const __half* src = g_wt + ((size_t)wsel * DK + (r & 63)) * EMB + kt + c * 8;
            *(uint4*)((char*)Ws + r * XPB + c * 16) = *(const uint4*)src;
        }
        __syncthreads();

        // ---- prefetch next X tile (overlaps MMAs below) ----
        if (kt + 64 < EMB) {
            #pragma unroll
            for (int it = 0; it < 8; it++) {
                int idx = tid + it * 256;
                int r = idx >> 4, c4 = (idx & 15) * 4;
                float4 v = *(const float4*)(X + (size_t)(m0 + r) * EMB + kt + 64 + c4);
                xp[it].x = packh2(v.x, v.y);
                xp[it].y = packh2(v.z, v.w);
            }
        }

        #pragma unroll
        for (int ks = 0; ks < 4; ks++) {
            uint32_t a[4];
            a[0] = *(const uint32_t*)&Xs[(wm + g    ) * XP + ks * 16 + 2 * t4    ];
            a[1] = *(const uint32_t*)&Xs[(wm + g + 8) * XP + ks * 16 + 2 * t4    ];
            a[2] = *(const uint32_t*)&Xs[(wm + g    ) * XP + ks * 16 + 2 * t4 + 8];
            a[3] = *(const uint32_t*)&Xs[(wm + g + 8) * XP + ks * 16 + 2 * t4 + 8];
            #pragma unroll
            for (int nt = 0; nt < NT; nt++) {
                uint32_t b0 = *(const uint32_t*)&Ws[(nt * 8 + g) * XP + ks * 16 + 2 * t4    ];
                uint32_t b1 = *(const uint32_t*)&Ws[(nt * 8 + g) * XP + ks * 16 + 2 * t4 + 8];
                mma16(acc[nt], a, b0, b1);
            }
        }
        __syncthreads();
    }

    // ---- epilogue ----
    #pragma unroll
    for (int nt = 0; nt < NT; nt++) {
        const int col = (nt & 7) * 8 + 2 * t4;
        const int rowA = m0 + wm + g, rowB = rowA + 8;
        if (which == 0) {
            const float b0 = bq[col], b1 = bq[col + 1];
            float a0 = (acc[nt][0] + b0) * 0.125f, a1 = (acc[nt][1] + b1) * 0.125f;
            float a2 = (acc[nt][2] + b0) * 0.125f, a3 = (acc[nt][3] + b1) * 0.125f;
            *(uint32_t*)(g_q + (size_t)rowA * DK + col) = packh2(a0, a1);
            *(uint32_t*)(g_q + (size_t)rowB * DK + col) = packh2(a2, a3);
        } else if (nt < 8) {
            const float b0 = bk[col], b1 = bk[col + 1];
            *(uint32_t*)(g_k + (size_t)rowA * DK + col) = packh2(acc[nt][0] + b0, acc[nt][1] + b1);
            *(uint32_t*)(g_k + (size_t)rowB * DK + col) = packh2(acc[nt][2] + b0, acc[nt][3] + b1);
        } else {
            const float b0 = bv[col], b1 = bv[col + 1];
            g_vt[(size_t)(col    ) * MROWS + rowA] = __float2half_rn(acc[nt][0] + b0);
            g_vt[(size_t)(col + 1) * MROWS + rowA] = __float2half_rn(acc[nt][1] + b1);
            g_vt[(size_t)(col    ) * MROWS + rowB] = __float2half_rn(acc[nt][2] + b0);
            g_vt[(size_t)(col + 1) * MROWS + rowB] = __float2half_rn(acc[nt][3] + b1);
        }
    }
}

__global__ __launch_bounds__(256) void proj_fused(
    const float* __restrict__ in1, const float* __restrict__ in2,
    const float* __restrict__ bq, const float* __restrict__ bk,
    const float* __restrict__ bv)
{
    __shared__ __align__(16) __half Xs[128 * XP];
    __shared__ __align__(16) __half Ws[128 * XP];

    const int which = blockIdx.z;
    const float* X = (which == 0) ? in2 : in1;
    const int m0   = blockIdx.x * 128;
    const int tid  = threadIdx.x;
    const int warp = tid >> 5;
    const int lane = tid & 31;

    if (which == 0)
        proj_body<8>(X, Xs, Ws, 0, m0, tid, warp, lane, bq, bk, bv);
    else
        proj_body<16>(X, Xs, Ws, 1, m0, tid, warp, lane, bq, bk, bv);
}

// ============================================================
// Flash attention, fp16 m16n8k16, split-KV x4, cp.async 2-stage.
// CTA: 128 thr (4 warps x 16 q-rows = 64 q), 1024 keys per CTA.
// ============================================================
#define FP 88
#define FPB 176

__global__ __launch_bounds__(128) void flash_fp16()
{
    __shared__ __align__(16) __half Ks[2][64 * FP];   // [key][d]
    __shared__ __align__(16) __half Vs[2][64 * FP];   // [d][key]

    const int tid  = threadIdx.x;
    const int warp = tid >> 5;
    const int lane = tid & 31;
    const int g    = lane >> 2;
    const int t4   = lane & 3;
    const int b    = blockIdx.y;
    const int sp   = blockIdx.z;
    const int q0   = blockIdx.x * 64 + warp * 16;
    const int kt0  = sp * KEYS_PER_SPLIT;

    const uint32_t ks_s[2] = {smem_u32(Ks[0]), smem_u32(Ks[1])};
    const uint32_t vs_s[2] = {smem_u32(Vs[0]), smem_u32(Vs[1])};
    const __half* Kg0 = g_k + (size_t)(b * SEQ) * DK;

    // issue one 64-key tile's K/V copies into stage st
    auto issue_tile = [&](int kt, int st) {
        const char* Kg = (const char*)(Kg0 + (size_t)kt * DK);
        const char* Vg = (const char*)(g_vt + (size_t)(b * SEQ + kt));
        #pragma unroll
        for (int it = 0; it < 4; it++) {
            int i = tid + it * 128;
            int r = i >> 3, c = i & 7;
            cpa16(ks_s[st] + r * FPB + c * 16, Kg + r * 128 + c * 16);
            cpa16(vs_s[st] + r * FPB + c * 16, Vg + (size_t)r * (MROWS * 2) + c * 16);
        }
        asm volatile("cp.async.commit_group;" ::: "memory");
    };

    // ---- Q fragments (scaled by 1/8 already) ----
    issue_tile(kt0, 0);

    uint32_t q[16];
    {
        const __half* Qg = g_q + (size_t)(b * SEQ + q0) * DK;
        #pragma unroll
        for (int ks = 0; ks < 4; ks++) {
            q[ks * 4 + 0] = *(const uint32_t*)(Qg + (size_t)(g    ) * DK + ks * 16 + 2 * t4    );
            q[ks * 4 + 1] = *(const uint32_t*)(Qg + (size_t)(g + 8) * DK + ks * 16 + 2 * t4    );
            q[ks * 4 + 2] = *(const uint32_t*)(Qg + (size_t)(g    ) * DK + ks * 16 + 2 * t4 + 8);
            q[ks * 4 + 3] = *(const uint32_t*)(Qg + (size_t)(g + 8) * DK + ks * 16 + 2 * t4 + 8);
        }
    }

    float o[8][4];
    #pragma unroll
    for (int nt = 0; nt < 8; nt++)
        #pragma unroll
        for (int j = 0; j < 4; j++) o[nt][j] = 0.f;
    float mA = -INFINITY, mB = -INFINITY, lA = 0.f, lB = 0.f;

    #pragma unroll 1
    for (int t = 0; t < NTILES; t++) {
        const int st = t & 1;
        if (t + 1 < NTILES) {
            issue_tile(kt0 + (t + 1) * 64, st ^ 1);
            asm volatile("cp.async.wait_group 1;" ::: "memory");
        } else {
            asm volatile("cp.async.wait_group 0;" ::: "memory");
        }
        __syncthreads();

        const char* KsB = (const char*)Ks[st];
        const char* VsB = (const char*)Vs[st];

        // ---- S = Q @ K^T ----
        float s[8][4];
        #pragma unroll
        for (int nt = 0; nt < 8; nt++)
            #pragma unroll
            for (int j = 0; j < 4; j++) s[nt][j] = 0.f;

        #pragma unroll
        for (int ks = 0; ks < 4; ks++) {
            #pragma unroll
            for (int nt = 0; nt < 8; nt++) {
                const char* kb = KsB + (nt * 8 + g) * FPB + ks * 32 + t4 * 4;
                uint32_t b0 = *(const uint32_t*)kb;
                uint32_t b1 = *(const uint32_t*)(kb + 16);
                mma16(s[nt], &q[ks * 4], b0, b1);
            }
        }

        // ---- online softmax ----
        float mxA = -INFINITY, mxB = -INFINITY;
        #pragma unroll
        for (int nt = 0; nt < 8; nt++) {
            mxA = fmaxf(mxA, fmaxf(s[nt][0], s[nt][1]));
            mxB = fmaxf(mxB, fmaxf(s[nt][2], s[nt][3]));
        }
        mxA = fmaxf(mxA, __shfl_xor_sync(0xffffffffu, mxA, 1));
        mxA = fmaxf(mxA, __shfl_xor_sync(0xffffffffu, mxA, 2));
        mxB = fmaxf(mxB, __shfl_xor_sync(0xffffffffu, mxB, 1));
        mxB = fmaxf(mxB, __shfl_xor_sync(0xffffffffu, mxB, 2));

        const float mnA = fmaxf(mA, mxA), mnB = fmaxf(mB, mxB);
        const float cA = __expf(mA - mnA), cB = __expf(mB - mnB);

        float sumA = 0.f, sumB = 0.f;
        #pragma unroll
        for (int nt = 0; nt < 8; nt++) {
            s[nt][0] = __expf(s[nt][0] - mnA);
            s[nt][1] = __expf(s[nt][1] - mnA);
            s[nt][2] = __expf(s[nt][2] - mnB);
            s[nt][3] = __expf(s[nt][3] - mnB);
            sumA += s[nt][0] + s[nt][1];
            sumB += s[nt][2] + s[nt][3];
        }
        sumA += __shfl_xor_sync(0xffffffffu, sumA, 1);
        sumA += __shfl_xor_sync(0xffffffffu, sumA, 2);
        sumB += __shfl_xor_sync(0xffffffffu, sumB, 1);
        sumB += __shfl_xor_sync(0xffffffffu, sumB, 2);
        lA = lA * cA + sumA;  mA = mnA;
        lB = lB * cB + sumB;  mB = mnB;

        #pragma unroll
        for (int nt = 0; nt < 8; nt++) {
            o[nt][0] *= cA; o[nt][1] *= cA;
            o[nt][2] *= cB; o[nt][3] *= cB;
        }

        // ---- O += P @ V ----
        #pragma unroll
        for (int ks = 0; ks < 4; ks++) {
            uint32_t a[4];
            a[0] = packh2(s[2 * ks    ][0], s[2 * ks    ][1]);
            a[1] = packh2(s[2 * ks    ][2], s[2 * ks    ][3]);
            a[2] = packh2(s[2 * ks + 1][0], s[2 * ks + 1][1]);
            a[3] = packh2(s[2 * ks + 1][2], s[2 * ks + 1][3]);
            #pragma unroll
            for (int nt = 0; nt < 8; nt++) {
                const char* vb = VsB + (nt * 8 + g) * FPB + ks * 32 + t4 * 4;
                uint32_t b0 = *(const uint32_t*)vb;
                uint32_t b1 = *(const uint32_t*)(vb + 16);
                mma16(o[nt], a, b0, b1);
            }
        }
        __syncthreads();
    }

    // ---- epilogue: unnormalized partials ----
    const int rowA = b * SEQ + q0 + g;
    const int rowB = rowA + 8;
    float* poA = g_po + ((size_t)sp * MROWS + rowA) * DK;
    float* poB = g_po + ((size_t)sp * MROWS + rowB) * DK;
    #pragma unroll
    for (int nt = 0; nt < 8; nt++) {
        const int col = nt * 8 + 2 * t4;
        *(float2*)(poA + col) = make_float2(o[nt][0], o[nt][1]);
        *(float2*)(poB + col) = make_float2(o[nt][2], o[nt][3]);
    }
    if (t4 == 0) {
        g_pm[sp * MROWS + rowA] = mA;  g_pl[sp * MROWS + rowA] = lA;
        g_pm[sp * MROWS + rowB] = mB;  g_pl[sp * MROWS + rowB] = lB;
    }
}

// ============================================================
// Merge NSPLIT partials -> final normalized output
// ============================================================
__global__ __launch_bounds__(256) void merge_splits(float* __restrict__ out)
{
    const int i = blockIdx.x * 256 + threadIdx.x;
    const int row = i >> 4, c4 = (i & 15) * 4;

    float m = -INFINITY;
    #pragma unroll
    for (int s = 0; s < NSPLIT; s++)
        m = fmaxf(m, g_pm[s * MROWS + row]);

    float lsum = 0.f;
    float4 acc = {0.f, 0.f, 0.f, 0.f};
    #pragma unroll
    for (int s = 0; s < NSPLIT; s++) {
        const float w = __expf(g_pm[s * MROWS + row] - m);
        lsum += w * g_pl[s * MROWS + row];
        const float4 o = *(const float4*)(g_po + ((size_t)s * MROWS + row) * DK + c4);
        acc.x += w * o.x; acc.y += w * o.y;
        acc.z += w * o.z; acc.w += w * o.w;
    }
    const float inv = 1.f / lsum;
    float4 r = {acc.x * inv, acc.y * inv, acc.z * inv, acc.w * inv};
    *(float4*)(out + (size_t)row * DK + c4) = r;
}

// ---------------- launch ----------------
extern "C" void kernel_launch(void* const* d_in, const int* in_sizes, int n_in,
                              void* d_out, int out_size)
{
    const float* input1 = (const float*)d_in[0];
    const float* input2 = (const float*)d_in[1];
    const float* Wq = (const float*)d_in[2];
    const float* bq = (const float*)d_in[3];
    const float* Wk = (const float*)d_in[4];
    const float* bk = (const float*)d_in[5];
    const float* Wv = (const float*)d_in[6];
    const float* bv = (const float*)d_in[7];
    float* out = (float*)d_out;

    (void)in_sizes; (void)n_in; (void)out_size;

    prep_w<<<192, 256>>>(Wq, Wk, Wv);

    dim3 pgrid(MROWS / 128, 1, 2);
    proj_fused<<<pgrid, 256>>>(input1, input2, bq, bk, bv);

    dim3 fgrid(SEQ / 64, BATCH, NSPLIT);
    flash_fp16<<<fgrid, 128>>>();

    merge_splits<<<(MROWS * 16) / 256, 256>>>(out);
}